// round 9
// baseline (speedup 1.0000x reference)
#include <cuda_runtime.h>
#include <cstdint>

#define NROWS   4096
#define S_SLOTS 200
#define X_DIM   64
#define M_DIM   364
#define O_DIM   64
#define F4      91                    // M_DIM / 4
#define EPS     1e-6f
#define NT      256
#define NW      8
#define SLOT_B  (M_DIM * 4)           // 1456 bytes per slot (16B multiple)
#define DEPTH   3
#define SPW     (S_SLOTS / NW)        // 25 slots per warp
#define WSTRIDE_B (NW * SLOT_B)       // byte stride between a warp's slots

__device__ __forceinline__ void mbar_init(unsigned a, unsigned cnt) {
    asm volatile("mbarrier.init.shared.b64 [%0], %1;" :: "r"(a), "r"(cnt) : "memory");
}
__device__ __forceinline__ void mbar_expect_tx(unsigned a, unsigned bytes) {
    asm volatile("mbarrier.arrive.expect_tx.shared.b64 _, [%0], %1;" :: "r"(a), "r"(bytes) : "memory");
}
__device__ __forceinline__ void tma_bulk_g2s(unsigned dst, const void* src, unsigned bytes, unsigned mbar) {
    asm volatile("cp.async.bulk.shared::cluster.global.mbarrier::complete_tx::bytes [%0], [%1], %2, [%3];"
                 :: "r"(dst), "l"(src), "r"(bytes), "r"(mbar) : "memory");
}
__device__ __forceinline__ void mbar_wait(unsigned a, unsigned phase) {
    asm volatile(
        "{\n\t"
        ".reg .pred P;\n\t"
        "WL%=:\n\t"
        "mbarrier.try_wait.parity.acquire.cta.shared::cta.b64 P, [%0], %1, 0x989680;\n\t"
        "@P bra WD%=;\n\t"
        "bra WL%=;\n\t"
        "WD%=:\n\t"
        "}" :: "r"(a), "r"(phase) : "memory");
}

__global__ __launch_bounds__(NT, 5)
void mem_attn_kernel(const float* __restrict__ x,
                     const float* __restrict__ mem,
                     const float* __restrict__ W_x,
                     const float* __restrict__ b_x,
                     const float* __restrict__ W_out,
                     const float* __restrict__ b_out,
                     float* __restrict__ out)
{
    // per-warp private ring buffers + per-warp per-stage mbarriers
    __shared__ __align__(16) char sbuf[NW][DEPTH][SLOT_B];   // 34944 B
    __shared__ __align__(8)  uint64_t mbar[NW][DEPTH];
    __shared__ __align__(16) float sh_h[M_DIM];
    __shared__ float sh_x[X_DIM];
    __shared__ float sh_red[NW];
    __shared__ float sh_wsum[NW];

    const int n    = blockIdx.x;
    const int t    = threadIdx.x;
    const int lane = t & 31;
    const int w    = t >> 5;

    const float* memn = mem + (size_t)n * S_SLOTS * M_DIM;
    const bool has2   = lane < (F4 - 64);          // lanes 0..26

    const unsigned sb0 = (unsigned)__cvta_generic_to_shared(&sbuf[w][0][0]);
    const unsigned mb0 = (unsigned)__cvta_generic_to_shared(&mbar[w][0]);

    // running global pointer for this warp's slot stream (slots w, w+8, ...)
    const char* gcur = (const char*)memn + (size_t)w * SLOT_B;

    // ---- prologue: lane0 inits this warp's mbarriers and launches DEPTH TMAs ----
    if (lane == 0) {
        #pragma unroll
        for (int d = 0; d < DEPTH; d++) mbar_init(mb0 + 8u * d, 1);
        asm volatile("fence.mbarrier_init.release.cluster;" ::: "memory");
        #pragma unroll
        for (int d = 0; d < DEPTH; d++) {
            mbar_expect_tx(mb0 + 8u * d, SLOT_B);
            tma_bulk_g2s(sb0 + d * SLOT_B, gcur + (size_t)d * WSTRIDE_B, SLOT_B, mb0 + 8u * d);
        }
    }
    gcur += (size_t)DEPTH * WSTRIDE_B;   // uniform advance (only lane0 dereferences)

    // ---- h = relu(x @ W_x + b_x) and 1/||h||  (overlaps prologue TMAs) ----
    if (t < X_DIM) sh_x[t] = x[(size_t)n * X_DIM + t];
    __syncthreads();   // also publishes mbarrier inits to all lanes

    float hn_part = 0.f;
    for (int j = t; j < M_DIM; j += NT) {
        float a = b_x[j];
        #pragma unroll 16
        for (int i = 0; i < X_DIM; i++) a = fmaf(sh_x[i], W_x[i * M_DIM + j], a);
        a = fmaxf(a, 0.f);
        sh_h[j] = a;
        hn_part = fmaf(a, a, hn_part);
    }
    #pragma unroll
    for (int o = 16; o > 0; o >>= 1) hn_part += __shfl_xor_sync(0xffffffffu, hn_part, o);
    if (lane == 0) sh_red[w] = hn_part;
    __syncthreads();
    float hsum = 0.f;
    #pragma unroll
    for (int i = 0; i < NW; i++) hsum += sh_red[i];
    const float inv_hnorm = 1.f / fmaxf(sqrtf(hsum), EPS);

    const float4* sh_h4 = reinterpret_cast<const float4*>(sh_h);

    // ---- barrier-free mainloop: each warp streams its own 25 slots via TMA ----
    float4 acc0 = make_float4(0.f, 0.f, 0.f, 0.f);
    float4 acc1 = make_float4(0.f, 0.f, 0.f, 0.f);
    float4 acc2 = make_float4(0.f, 0.f, 0.f, 0.f);
    float rsum = 0.f;

    int rb = 0, ph = 0;   // ring index and mbarrier phase parity
    for (int i = 0; i < SPW; i++) {
        mbar_wait(mb0 + 8u * rb, (unsigned)ph);

        const float4* slot = reinterpret_cast<const float4*>(&sbuf[w][rb][0]);
        float4 v0 = slot[lane];
        float4 v1 = slot[lane + 32];
        float4 v2 = has2 ? slot[lane + 64] : make_float4(0.f, 0.f, 0.f, 0.f);
        float4 h0 = sh_h4[lane];
        float4 h1 = sh_h4[lane + 32];
        float4 h2 = has2 ? sh_h4[lane + 64] : make_float4(0.f, 0.f, 0.f, 0.f);

        // EARLY refill: warp-wide LDS above issued in lockstep before lane0
        // reaches here; the TMA smem write cannot land for >=300cyc while the
        // LDS complete in ~29cyc -> safe to rearm and overwrite.
        if (lane == 0 && i + DEPTH < SPW) {
            mbar_expect_tx(mb0 + 8u * rb, SLOT_B);
            tma_bulk_g2s(sb0 + rb * SLOT_B, gcur, SLOT_B, mb0 + 8u * rb);
        }
        gcur += WSTRIDE_B;

        float dot = v0.x*h0.x + v0.y*h0.y + v0.z*h0.z + v0.w*h0.w
                  + v1.x*h1.x + v1.y*h1.y + v1.z*h1.z + v1.w*h1.w
                  + v2.x*h2.x + v2.y*h2.y + v2.z*h2.z + v2.w*h2.w;
        float nsq = v0.x*v0.x + v0.y*v0.y + v0.z*v0.z + v0.w*v0.w
                  + v1.x*v1.x + v1.y*v1.y + v1.z*v1.z + v1.w*v1.w
                  + v2.x*v2.x + v2.y*v2.y + v2.z*v2.z + v2.w*v2.w;
        #pragma unroll
        for (int o = 16; o > 0; o >>= 1) {
            dot += __shfl_xor_sync(0xffffffffu, dot, o);
            nsq += __shfl_xor_sync(0xffffffffu, nsq, o);
        }

        // cosine sim in [-1,1] -> exp() safe without max subtraction
        const float sim = dot * inv_hnorm / fmaxf(sqrtf(nsq), EPS);
        const float e = __expf(sim);
        rsum += e;

        acc0.x = fmaf(e, v0.x, acc0.x); acc0.y = fmaf(e, v0.y, acc0.y);
        acc0.z = fmaf(e, v0.z, acc0.z); acc0.w = fmaf(e, v0.w, acc0.w);
        acc1.x = fmaf(e, v1.x, acc1.x); acc1.y = fmaf(e, v1.y, acc1.y);
        acc1.z = fmaf(e, v1.z, acc1.z); acc1.w = fmaf(e, v1.w, acc1.w);
        acc2.x = fmaf(e, v2.x, acc2.x); acc2.y = fmaf(e, v2.y, acc2.y);
        acc2.z = fmaf(e, v2.z, acc2.z); acc2.w = fmaf(e, v2.w, acc2.w);

        if (++rb == DEPTH) { rb = 0; ph ^= 1; }
    }

    // ---- merge warps; rings fully consumed -> reuse as scratch ----
    asm volatile("fence.proxy.async.shared::cta;" ::: "memory");
    float* accbuf = reinterpret_cast<float*>(sbuf);           // [NW][M_DIM]
    float* g      = accbuf + NW * M_DIM;                      // [M_DIM]
    float (*outb)[O_DIM] = reinterpret_cast<float (*)[O_DIM]>(g + M_DIM);

    if (lane == 0) sh_wsum[w] = rsum;
    __syncthreads();   // all warps done with their rings before scratch reuse
    {
        float4* dst = reinterpret_cast<float4*>(accbuf + w * M_DIM);
        dst[lane]      = acc0;
        dst[lane + 32] = acc1;
        if (has2) dst[lane + 64] = acc2;
    }
    __syncthreads();

    float total = 0.f;
    #pragma unroll
    for (int i = 0; i < NW; i++) total += sh_wsum[i];

    const float inv = 1.f / (total * (float)S_SLOTS);
    for (int j = t; j < M_DIM; j += NT) {
        float p = 0.f;
        #pragma unroll
        for (int i = 0; i < NW; i++) p += accbuf[i * M_DIM + j];
        g[j] = p * inv * sh_h[j];
    }
    __syncthreads();

    // ---- out = relu((pooled*h) @ W_out + b_out) ----
    {
        const int oc = t & 63;
        const int c  = t >> 6;           // 4 chunks of 91
        float a = 0.f;
        const int m0 = c * F4;
        #pragma unroll 13
        for (int m = m0; m < m0 + F4; m++) a = fmaf(g[m], W_out[m * O_DIM + oc], a);
        outb[c][oc] = a;
    }
    __syncthreads();
    if (t < O_DIM) {
        float a = outb[0][t] + outb[1][t] + outb[2][t] + outb[3][t] + b_out[t];
        out[(size_t)n * O_DIM + t] = fmaxf(a, 0.f);
    }
}

extern "C" void kernel_launch(void* const* d_in, const int* in_sizes, int n_in,
                              void* d_out, int out_size)
{
    const float* x     = (const float*)d_in[0];
    const float* mem   = (const float*)d_in[1];
    const float* W_x   = (const float*)d_in[2];
    const float* b_x   = (const float*)d_in[3];
    const float* W_out = (const float*)d_in[4];
    const float* b_out = (const float*)d_in[5];
    float* out = (float*)d_out;

    mem_attn_kernel<<<NROWS, NT>>>(x, mem, W_x, b_x, W_out, b_out, out);
}

// round 10
// speedup vs baseline: 1.1706x; 1.1706x over previous
#include <cuda_runtime.h>

#define NROWS   4096
#define S_SLOTS 200
#define X_DIM   64
#define M_DIM   364
#define O_DIM   64
#define F4      91                    // M_DIM / 4
#define EPS     1e-6f
#define NT      256
#define NW      8
#define SLOT_B  (M_DIM * 4)           // 1456 bytes per slot in gmem
#define SLOT_P  1536                  // padded smem slot stride (128B multiple)
#define DEPTH   3
#define SPW     (S_SLOTS / NW)        // 25 slots per warp
#define WSTRIDE_B (NW * SLOT_B)       // global byte stride between a warp's slots

__global__ __launch_bounds__(NT, 5)
void mem_attn_kernel(const float* __restrict__ x,
                     const float* __restrict__ mem,
                     const float* __restrict__ W_x,
                     const float* __restrict__ b_x,
                     const float* __restrict__ W_out,
                     const float* __restrict__ b_out,
                     float* __restrict__ out)
{
    // per-warp private ring buffers, slots padded to 128B alignment
    __shared__ __align__(128) char  sbuf[NW][DEPTH][SLOT_P];  // 36864 B
    __shared__ __align__(16) float sh_h[M_DIM];
    __shared__ float sh_x[X_DIM];
    __shared__ float sh_red[NW];
    __shared__ float sh_wsum[NW];

    const int n    = blockIdx.x;
    const int t    = threadIdx.x;
    const int lane = t & 31;
    const int w    = t >> 5;

    const float* memn = mem + (size_t)n * S_SLOTS * M_DIM;
    const bool has2   = lane < (F4 - 64);          // lanes 0..26
    const int  off0   = lane * 16;                 // byte offsets within slot
    const int  off1   = off0 + 512;
    const int  off2   = off0 + 1024;

    const unsigned swarp = (unsigned)__cvta_generic_to_shared(&sbuf[w][0][0]);

    // running global pointer for this warp's slot stream (slot w, w+8, ...)
    const char* gcur = (const char*)memn + (size_t)w * SLOT_B;

    // ---- prologue: fill this warp's ring (slots w, w+8, w+16) ----
    #pragma unroll
    for (int d = 0; d < DEPTH; d++) {
        const unsigned s = swarp + d * SLOT_P;
        asm volatile("cp.async.cg.shared.global [%0], [%1], 16;" :: "r"(s + off0), "l"(gcur + off0));
        asm volatile("cp.async.cg.shared.global [%0], [%1], 16;" :: "r"(s + off1), "l"(gcur + off1));
        if (has2)
            asm volatile("cp.async.cg.shared.global [%0], [%1], 16;" :: "r"(s + off2), "l"(gcur + off2));
        asm volatile("cp.async.commit_group;");
        gcur += WSTRIDE_B;
    }

    // ---- h = relu(x @ W_x + b_x) and 1/||h||  (overlaps prologue copies) ----
    if (t < X_DIM) sh_x[t] = x[(size_t)n * X_DIM + t];
    __syncthreads();

    float hn_part = 0.f;
    for (int j = t; j < M_DIM; j += NT) {
        float a = b_x[j];
        #pragma unroll 16
        for (int i = 0; i < X_DIM; i++) a = fmaf(sh_x[i], W_x[i * M_DIM + j], a);
        a = fmaxf(a, 0.f);
        sh_h[j] = a;
        hn_part = fmaf(a, a, hn_part);
    }
    #pragma unroll
    for (int o = 16; o > 0; o >>= 1) hn_part += __shfl_xor_sync(0xffffffffu, hn_part, o);
    if (lane == 0) sh_red[w] = hn_part;
    __syncthreads();
    float hsum = 0.f;
    #pragma unroll
    for (int i = 0; i < NW; i++) hsum += sh_red[i];
    const float inv_hnorm = 1.f / fmaxf(sqrtf(hsum), EPS);

    const float4* sh_h4 = reinterpret_cast<const float4*>(sh_h);
    const bool odd = (lane & 1);

    // ---- barrier-free mainloop: each warp streams its own 25 slots ----
    float4 acc0 = make_float4(0.f, 0.f, 0.f, 0.f);
    float4 acc1 = make_float4(0.f, 0.f, 0.f, 0.f);
    float4 acc2 = make_float4(0.f, 0.f, 0.f, 0.f);
    float rsum = 0.f;

    int rb = 0;   // ring index = i % DEPTH
    for (int i = 0; i < SPW; i++) {
        asm volatile("cp.async.wait_group %0;" :: "n"(DEPTH - 1));
        // each lane reads exactly the float4s it copied -> per-thread
        // cp.async visibility suffices; no sync of any kind needed.
        const float4* slot = reinterpret_cast<const float4*>(&sbuf[w][rb][0]);
        float4 v0 = slot[lane];
        float4 v1 = slot[lane + 32];
        float4 v2 = has2 ? slot[lane + 64] : make_float4(0.f, 0.f, 0.f, 0.f);
        float4 h0 = sh_h4[lane];
        float4 h1 = sh_h4[lane + 32];
        float4 h2 = has2 ? sh_h4[lane + 64] : make_float4(0.f, 0.f, 0.f, 0.f);

        // EARLY refill: LDS above complete in ~29cyc; the cp.async smem write
        // cannot arrive for >=300cyc, same-thread same-address ops issue in
        // program order -> safe to overwrite-in-flight.
        if (i + DEPTH < SPW) {
            const unsigned s = swarp + rb * SLOT_P;
            asm volatile("cp.async.cg.shared.global [%0], [%1], 16;" :: "r"(s + off0), "l"(gcur + off0));
            asm volatile("cp.async.cg.shared.global [%0], [%1], 16;" :: "r"(s + off1), "l"(gcur + off1));
            if (has2)
                asm volatile("cp.async.cg.shared.global [%0], [%1], 16;" :: "r"(s + off2), "l"(gcur + off2));
            gcur += WSTRIDE_B;
        }
        asm volatile("cp.async.commit_group;");  // empty groups keep count uniform

        float dp = v0.x*h0.x + v0.y*h0.y + v0.z*h0.z + v0.w*h0.w
                 + v1.x*h1.x + v1.y*h1.y + v1.z*h1.z + v1.w*h1.w
                 + v2.x*h2.x + v2.y*h2.y + v2.z*h2.z + v2.w*h2.w;
        float np = v0.x*v0.x + v0.y*v0.y + v0.z*v0.z + v0.w*v0.w
                 + v1.x*v1.x + v1.y*v1.y + v1.z*v1.z + v1.w*v1.w
                 + v2.x*v2.x + v2.y*v2.y + v2.z*v2.z + v2.w*v2.w;

        // parity-packed reduction: 6 shfls instead of 10.
        // even lanes carry the dot sum, odd lanes the nsq sum, then swap back.
        float xv = odd ? np : dp;
        float yv = odd ? dp : np;
        xv += __shfl_xor_sync(0xffffffffu, yv, 1);
        #pragma unroll
        for (int o = 2; o <= 16; o <<= 1) xv += __shfl_xor_sync(0xffffffffu, xv, o);
        const float ov = __shfl_xor_sync(0xffffffffu, xv, 1);
        const float dot = odd ? ov : xv;
        const float nsq = odd ? xv : ov;

        // cosine sim in [-1,1] -> exp() safe without max subtraction
        const float sim = dot * inv_hnorm / fmaxf(sqrtf(nsq), EPS);
        const float e = __expf(sim);
        rsum += e;

        acc0.x = fmaf(e, v0.x, acc0.x); acc0.y = fmaf(e, v0.y, acc0.y);
        acc0.z = fmaf(e, v0.z, acc0.z); acc0.w = fmaf(e, v0.w, acc0.w);
        acc1.x = fmaf(e, v1.x, acc1.x); acc1.y = fmaf(e, v1.y, acc1.y);
        acc1.z = fmaf(e, v1.z, acc1.z); acc1.w = fmaf(e, v1.w, acc1.w);
        acc2.x = fmaf(e, v2.x, acc2.x); acc2.y = fmaf(e, v2.y, acc2.y);
        acc2.z = fmaf(e, v2.z, acc2.z); acc2.w = fmaf(e, v2.w, acc2.w);

        rb = (rb == DEPTH - 1) ? 0 : rb + 1;
    }

    // ---- merge warps; all remaining groups are empty, data consumed ----
    float* accbuf = reinterpret_cast<float*>(sbuf);           // [NW][M_DIM]
    float* g      = accbuf + NW * M_DIM;                      // [M_DIM]
    float (*outb)[O_DIM] = reinterpret_cast<float (*)[O_DIM]>(g + M_DIM);

    if (lane == 0) sh_wsum[w] = rsum;
    __syncthreads();   // all warps done with their rings before scratch reuse
    {
        float4* dst = reinterpret_cast<float4*>(accbuf + w * M_DIM);
        dst[lane]      = acc0;
        dst[lane + 32] = acc1;
        if (has2) dst[lane + 64] = acc2;
    }
    __syncthreads();

    float total = 0.f;
    #pragma unroll
    for (int i = 0; i < NW; i++) total += sh_wsum[i];

    const float inv = 1.f / (total * (float)S_SLOTS);
    for (int j = t; j < M_DIM; j += NT) {
        float p = 0.f;
        #pragma unroll
        for (int i = 0; i < NW; i++) p += accbuf[i * M_DIM + j];
        g[j] = p * inv * sh_h[j];
    }
    __syncthreads();

    // ---- out = relu((pooled*h) @ W_out + b_out) ----
    {
        const int oc = t & 63;
        const int c  = t >> 6;           // 4 chunks of 91
        float a = 0.f;
        const int m0 = c * F4;
        #pragma unroll 13
        for (int m = m0; m < m0 + F4; m++) a = fmaf(g[m], W_out[m * O_DIM + oc], a);
        outb[c][oc] = a;
    }
    __syncthreads();
    if (t < O_DIM) {
        float a = outb[0][t] + outb[1][t] + outb[2][t] + outb[3][t] + b_out[t];
        out[(size_t)n * O_DIM + t] = fmaxf(a, 0.f);
    }
}

extern "C" void kernel_launch(void* const* d_in, const int* in_sizes, int n_in,
                              void* d_out, int out_size)
{
    const float* x     = (const float*)d_in[0];
    const float* mem   = (const float*)d_in[1];
    const float* W_x   = (const float*)d_in[2];
    const float* b_x   = (const float*)d_in[3];
    const float* W_out = (const float*)d_in[4];
    const float* b_out = (const float*)d_in[5];
    float* out = (float*)d_out;

    mem_attn_kernel<<<NROWS, NT>>>(x, mem, W_x, b_x, W_out, b_out, out);
}